// round 14
// baseline (speedup 1.0000x reference)
#include <cuda_runtime.h>
#include <cuda_bf16.h>
#include <cstdint>

// ---------------------------------------------------------------------------
// STDP delta_w on GB300 — base-sm_103-legal tensor core path (mma.sync bf16).
//
//   trace_t = 0.5*trace_{t-1} + in_t
//   dw[o,i] = sum_{t,b} trace[t,b,i] * out[t,b,o]
//
// R13: correction kernel was REDG-bound (4.7M atomic lane-ops), not
// compute-bound. New corr: grid (9,4) = 36 CTAs, each accumulating 4 chunks
// in registers (double-buffered smem, reg prefetch) -> ONE red.global.add
// set per CTA = 4x fewer atomics. Main kernel unchanged (at ~95% of its
// streaming roofline).
//   dw = sum_c dw_intra(c) + sum_{c>=1} TE(c-1)^T * G(c)
// ---------------------------------------------------------------------------

#define T_STEPS 2048
#define B_DIM   128
#define N_IN    256
#define N_OUT   128
#define GT      37                  // time chunks (len 55 or 56)
#define KB      32
#define NBS     (B_DIM / KB)        // 4
#define NTHR    512

// Static smem, main kernel (48 KB):
#define TR_OFF   0
#define TR_BSZ   16384
#define OT_OFF   32768
#define OT_BSZ   8192
#define SM_TOTAL 49152

// Corr kernel static smem: 2 bufs x (TR slice 16KB + OT slice 8KB) = 48 KB
#define CR_BUF   24576
#define CR_TR    0
#define CR_OT    16384
#define CR_TOT   49152
#define CPC      4                  // chunks per corr CTA (36 = 9*4)

#define IN_SLAB  (B_DIM * N_IN  * 4)   // bytes per timestep of gin
#define OUT_SLAB (B_DIM * N_OUT / 4)   // float4 per timestep of gout

#define BF_HALF2 0x3F003F00u           // bf16x2 (0.5, 0.5)

// cross-chunk scratch, bf16x2 packed
__device__ uint32_t g_TE_u[GT * B_DIM * (N_IN / 2)];    // [chunk][b][i/2]
__device__ uint32_t g_G_u [GT * B_DIM * (N_OUT / 2)];   // [chunk][b][o/2]

__device__ __forceinline__ uint32_t smem_u32(const void* p) {
    uint32_t a;
    asm("{ .reg .u64 t; cvta.to.shared.u64 t, %1; cvt.u32.u64 %0, t; }" : "=r"(a) : "l"(p));
    return a;
}

__device__ __forceinline__ void ldsm4t(uint32_t* d, uint32_t a) {
    asm volatile("ldmatrix.sync.aligned.m8n8.x4.trans.shared.b16 {%0,%1,%2,%3}, [%4];"
                 : "=r"(d[0]), "=r"(d[1]), "=r"(d[2]), "=r"(d[3]) : "r"(a));
}

__device__ __forceinline__ void mma16816(float* d, const uint32_t* a, const uint32_t* b) {
    asm volatile(
        "mma.sync.aligned.m16n8k16.row.col.f32.bf16.bf16.f32 "
        "{%0,%1,%2,%3},{%4,%5,%6,%7},{%8,%9},{%0,%1,%2,%3};"
        : "+f"(d[0]), "+f"(d[1]), "+f"(d[2]), "+f"(d[3])
        : "r"(a[0]), "r"(a[1]), "r"(a[2]), "r"(a[3]), "r"(b[0]), "r"(b[1]));
}

__device__ __forceinline__ uint32_t hfma2(uint32_t a, uint32_t b, uint32_t c) {
    uint32_t d;
    asm("fma.rn.bf16x2 %0, %1, %2, %3;" : "=r"(d) : "r"(a), "r"(b), "r"(c));
    return d;
}

__device__ __forceinline__ uint32_t cvt2bf(float hi, float lo) {
    uint32_t r;
    asm("cvt.rn.bf16x2.f32 %0, %1, %2;" : "=r"(r) : "f"(hi), "f"(lo));
    return r;
}

// ---------------------------------------------------------------------------
__global__ void __launch_bounds__(NTHR, 1)
stdp_main_kernel(const float* __restrict__ gin,   // [T, B, N_IN]
                 const float* __restrict__ gout,  // [T, B, N_OUT]
                 float* __restrict__ dw)          // [N_OUT, N_IN]
{
    __shared__ __align__(1024) char smem[SM_TOTAL];
    const uint32_t sb = smem_u32(smem);
    const int tid = threadIdx.x;
    const int w   = tid >> 5;
    const int l   = tid & 31;

    const int cx  = blockIdx.x;
    const int t0  = (cx * T_STEPS) / GT;
    const int t1  = ((cx + 1) * T_STEPS) / GT;
    const int len = t1 - t0;                 // 55 or 56
    const int b0  = blockIdx.y * KB;

    // ---- affine per-thread base offsets -------------------------------------
    const int bi  = tid >> 6;               // in-base batch row (0..7)
    const int i4  = (tid & 63) << 2;
    const int gi0 = ((b0 + bi) * (N_IN / 4) + (tid & 63)) * 16;      // bytes
    const uint32_t stsin0 = (uint32_t)(bi * 512 + (((i4 >> 3) ^ (bi & 7)) << 4)
                                       + ((i4 & 7) << 1));
    const int bo  = tid >> 5;               // out-base batch row (0..15)
    const int o4  = (tid & 31) << 2;
    const int go0 = (b0 + bo) * (N_OUT / 4) + (tid & 31);             // float4
    const uint32_t stsout0 = (uint32_t)(bo * 256 + (((o4 >> 3) ^ (bo & 7)) << 4)
                                        + ((o4 & 7) << 1));

    // ---- ldmatrix source addresses (relative to tile buf base) --------------
    const int wr = w >> 2, wc = w & 3;
    const int obase = wr * 32, ibase = wc * 64;

    uint32_t a_addr[2];
#pragma unroll
    for (int mt = 0; mt < 2; mt++) {
        int b  = (l & 7) + ((l >> 4) << 3);
        int ch = ((obase + mt * 16) >> 3) + ((l >> 3) & 1);
        a_addr[mt] = (uint32_t)(b * 256 + ((ch ^ (b & 7)) << 4));
    }
    uint32_t b_addr[4];
#pragma unroll
    for (int np = 0; np < 4; np++) {
        int b  = (l & 7) + (((l >> 3) & 1) << 3);
        int ch = ((ibase + np * 16) >> 3) + ((l >> 4) & 1);
        b_addr[np] = (uint32_t)(b * 512 + ((ch ^ (b & 7)) << 4));
    }

    // ---- state: bf16x2 trace in registers, bf16x2 G accumulator -------------
    uint32_t tr[8];
#pragma unroll
    for (int j = 0; j < 8; j++) tr[j] = 0u;
    uint32_t g4[4];
#pragma unroll
    for (int j = 0; j < 4; j++) g4[j] = 0u;
    uint32_t wgtv = BF_HALF2;   // 0.5^{s+1} packed

    float acc[2][8][4];
#pragma unroll
    for (int mt = 0; mt < 2; mt++)
#pragma unroll
        for (int nt = 0; nt < 8; nt++)
#pragma unroll
            for (int r = 0; r < 4; r++) acc[mt][nt][r] = 0.0f;

    // distance-1 register prefetch of in (4 x float4) and out (2 x float4)
    float4 vin[4], voA[2];
    {
        const char* src = (const char*)gin + (size_t)t0 * IN_SLAB + gi0;
#pragma unroll
        for (int q = 0; q < 4; q++)
            vin[q] = *reinterpret_cast<const float4*>(src + q * 8192);
        const float4* po = reinterpret_cast<const float4*>(gout)
                         + (size_t)t0 * OUT_SLAB + go0;
#pragma unroll
        for (int q = 0; q < 2; q++) voA[q] = po[q * 512];
    }

    auto produce = [&](int sp) {
        const int buf = sp & 1;
        char* td = smem + TR_OFF + buf * TR_BSZ + stsin0;
#pragma unroll
        for (int q = 0; q < 4; q++) {
            uint32_t i01 = cvt2bf(vin[q].y, vin[q].x);
            uint32_t i23 = cvt2bf(vin[q].w, vin[q].z);
            tr[2 * q]     = hfma2(tr[2 * q],     BF_HALF2, i01);
            tr[2 * q + 1] = hfma2(tr[2 * q + 1], BF_HALF2, i23);
            *reinterpret_cast<uint2*>(td + q * 4096) =
                make_uint2(tr[2 * q], tr[2 * q + 1]);
        }
        char* od = smem + OT_OFF + buf * OT_BSZ + stsout0;
#pragma unroll
        for (int q = 0; q < 2; q++) {
            uint32_t o01 = cvt2bf(voA[q].y, voA[q].x);
            uint32_t o23 = cvt2bf(voA[q].w, voA[q].z);
            *reinterpret_cast<uint2*>(od + q * 4096) = make_uint2(o01, o23);
            g4[2 * q]     = hfma2(o01, wgtv, g4[2 * q]);
            g4[2 * q + 1] = hfma2(o23, wgtv, g4[2 * q + 1]);
        }
        wgtv = hfma2(wgtv, BF_HALF2, 0u);   // wgt *= 0.5 (packed)
        if (sp + 1 < len) {
            const char* src = (const char*)gin + (size_t)(t0 + sp + 1) * IN_SLAB + gi0;
#pragma unroll
            for (int q = 0; q < 4; q++)
                vin[q] = *reinterpret_cast<const float4*>(src + q * 8192);
            const float4* po = reinterpret_cast<const float4*>(gout)
                             + (size_t)(t0 + sp + 1) * OUT_SLAB + go0;
#pragma unroll
            for (int q = 0; q < 2; q++) voA[q] = po[q * 512];
        }
    };

    auto do_mma = [&](int buf) {
        const uint32_t abase = sb + OT_OFF + buf * OT_BSZ;
        const uint32_t bbase = sb + TR_OFF + buf * TR_BSZ;
#pragma unroll
        for (int kb = 0; kb < 2; kb++) {
            uint32_t af[2][4];
            ldsm4t(af[0], abase + a_addr[0] + kb * 16 * 256);
            ldsm4t(af[1], abase + a_addr[1] + kb * 16 * 256);
#pragma unroll
            for (int np = 0; np < 4; np++) {
                uint32_t bf[4];
                ldsm4t(bf, bbase + b_addr[np] + kb * 16 * 512);
#pragma unroll
                for (int mt = 0; mt < 2; mt++) {
                    mma16816(acc[mt][2 * np],     af[mt], bf);
                    mma16816(acc[mt][2 * np + 1], af[mt], bf + 2);
                }
            }
        }
    };

    produce(0);
    __syncthreads();

    for (int s = 0; s < len; s++) {
        if ((w & 1) == 0) {
            do_mma(s & 1);
            if (s + 1 < len) produce(s + 1);
        } else {
            if (s + 1 < len) produce(s + 1);
            do_mma(s & 1);
        }
        __syncthreads();
    }

    // ---- store TE (final trace regs) and G to scratch -----------------------
    {
        uint32_t* te = g_TE_u + ((size_t)cx * B_DIM + (b0 + bi)) * (N_IN / 2)
                     + ((tid & 63) << 1);
#pragma unroll
        for (int q = 0; q < 4; q++)
            *reinterpret_cast<uint2*>(te + q * (8 * (N_IN / 2))) =
                make_uint2(tr[2 * q], tr[2 * q + 1]);
        uint32_t* gg = g_G_u + ((size_t)cx * B_DIM + (b0 + bo)) * (N_OUT / 2)
                     + ((tid & 31) << 1);
#pragma unroll
        for (int q = 0; q < 2; q++)
            *reinterpret_cast<uint2*>(gg + q * (16 * (N_OUT / 2))) =
                make_uint2(g4[2 * q], g4[2 * q + 1]);
    }

    // ---- epilogue: vector reductions into dw --------------------------------
#pragma unroll
    for (int mt = 0; mt < 2; mt++) {
#pragma unroll
        for (int nt = 0; nt < 8; nt++) {
            const int o = obase + mt * 16 + (l >> 2);
            const int i = ibase + nt * 8 + ((l & 3) << 1);
            float* p = dw + (size_t)o * N_IN + i;
            asm volatile("red.global.add.v2.f32 [%0], {%1,%2};"
                         :: "l"(p), "f"(acc[mt][nt][0]), "f"(acc[mt][nt][1]) : "memory");
            asm volatile("red.global.add.v2.f32 [%0], {%1,%2};"
                         :: "l"(p + 8 * N_IN), "f"(acc[mt][nt][2]), "f"(acc[mt][nt][3]) : "memory");
        }
    }
}

// ---------------------------------------------------------------------------
// Cross-chunk correction: dw += sum_c TE(c-1)^T * G(c).
// Grid (9, NBS): each CTA accumulates CPC=4 chunks of the K=32 batch slice
// into registers (double-buffered smem, reg prefetch), then ONE
// red.global.add set — 4x fewer atomics than one-chunk-per-CTA.
__global__ void __launch_bounds__(NTHR, 1)
stdp_corr_kernel(float* __restrict__ dw)
{
    __shared__ __align__(1024) char smem[CR_TOT];
    const uint32_t sb = smem_u32(smem);
    const int tid = threadIdx.x;
    const int w   = tid >> 5;
    const int l   = tid & 31;
    const int c0  = blockIdx.x * CPC + 1;    // chunks c0 .. c0+CPC-1
    const int b0  = blockIdx.y * KB;

    const int bi = tid >> 6;
    const int i4 = (tid & 63) << 2;
    const uint32_t stsin0 = (uint32_t)(bi * 512 + (((i4 >> 3) ^ (bi & 7)) << 4)
                                       + ((i4 & 7) << 1));
    const int bo = tid >> 5;
    const int o4 = (tid & 31) << 2;
    const uint32_t stsout0 = (uint32_t)(bo * 256 + (((o4 >> 3) ^ (bo & 7)) << 4)
                                        + ((o4 & 7) << 1));

    // per-thread gmem slice pointers (chunk stride added per iteration)
    const uint32_t* teP = g_TE_u + ((size_t)(c0 - 1) * B_DIM + (b0 + bi)) * (N_IN / 2)
                        + ((tid & 63) << 1);
    const uint32_t* ggP = g_G_u + ((size_t)c0 * B_DIM + (b0 + bo)) * (N_OUT / 2)
                        + ((tid & 31) << 1);
    const size_t teStride = (size_t)B_DIM * (N_IN / 2);    // per chunk
    const size_t ggStride = (size_t)B_DIM * (N_OUT / 2);

    // ---- ldmatrix addresses -------------------------------------------------
    const int wr = w >> 2, wc = w & 3;
    const int obase = wr * 32, ibase = wc * 64;

    uint32_t a_addr[2];
#pragma unroll
    for (int mt = 0; mt < 2; mt++) {
        int b  = (l & 7) + ((l >> 4) << 3);
        int ch = ((obase + mt * 16) >> 3) + ((l >> 3) & 1);
        a_addr[mt] = (uint32_t)(b * 256 + ((ch ^ (b & 7)) << 4));
    }
    uint32_t b_addr[4];
#pragma unroll
    for (int np = 0; np < 4; np++) {
        int b  = (l & 7) + (((l >> 3) & 1) << 3);
        int ch = ((ibase + np * 16) >> 3) + ((l >> 4) & 1);
        b_addr[np] = (uint32_t)(b * 512 + ((ch ^ (b & 7)) << 4));
    }

    float acc[2][8][4];
#pragma unroll
    for (int mt = 0; mt < 2; mt++)
#pragma unroll
        for (int nt = 0; nt < 8; nt++)
#pragma unroll
            for (int r = 0; r < 4; r++) acc[mt][nt][r] = 0.0f;

    // register prefetch of chunk j=0 slices
    uint2 teR[4], ggR[2];
#pragma unroll
    for (int q = 0; q < 4; q++)
        teR[q] = *reinterpret_cast<const uint2*>(teP + q * (8 * (N_IN / 2)));
#pragma unroll
    for (int q = 0; q < 2; q++)
        ggR[q] = *reinterpret_cast<const uint2*>(ggP + q * (16 * (N_OUT / 2)));

#pragma unroll
    for (int j = 0; j < CPC; j++) {
        const int buf = j & 1;
        // STS current chunk's slices into buf
        char* td = smem + buf * CR_BUF + CR_TR + stsin0;
#pragma unroll
        for (int q = 0; q < 4; q++)
            *reinterpret_cast<uint2*>(td + q * 4096) = teR[q];
        char* od = smem + buf * CR_BUF + CR_OT + stsout0;
#pragma unroll
        for (int q = 0; q < 2; q++)
            *reinterpret_cast<uint2*>(od + q * 4096) = ggR[q];

        // prefetch chunk j+1 into regs
        if (j + 1 < CPC) {
            const uint32_t* teN = teP + (size_t)(j + 1) * teStride;
            const uint32_t* ggN = ggP + (size_t)(j + 1) * ggStride;
#pragma unroll
            for (int q = 0; q < 4; q++)
                teR[q] = *reinterpret_cast<const uint2*>(teN + q * (8 * (N_IN / 2)));
#pragma unroll
            for (int q = 0; q < 2; q++)
                ggR[q] = *reinterpret_cast<const uint2*>(ggN + q * (16 * (N_OUT / 2)));
        }

        __syncthreads();

        // MMA on buf: K = 32 (2 kb blocks), accumulate across chunks
        const uint32_t abase = sb + buf * CR_BUF + CR_OT;
        const uint32_t bbase = sb + buf * CR_BUF + CR_TR;
#pragma unroll
        for (int kb = 0; kb < 2; kb++) {
            uint32_t af[2][4];
            ldsm4t(af[0], abase + a_addr[0] + kb * 16 * 256);
            ldsm4t(af[1], abase + a_addr[1] + kb * 16 * 256);
#pragma unroll
            for (int np = 0; np < 4; np++) {
                uint32_t bf[4];
                ldsm4t(bf, bbase + b_addr[np] + kb * 16 * 512);
#pragma unroll
                for (int mt = 0; mt < 2; mt++) {
                    mma16816(acc[mt][2 * np],     af[mt], bf);
                    mma16816(acc[mt][2 * np + 1], af[mt], bf + 2);
                }
            }
        }
        // no trailing barrier: next iteration writes the OTHER buffer, and the
        // next sync proves all warps consumed it two iterations ago.
    }

    // ---- single epilogue: vector reductions into dw -------------------------
#pragma unroll
    for (int mt = 0; mt < 2; mt++) {
#pragma unroll
        for (int nt = 0; nt < 8; nt++) {
            const int o = obase + mt * 16 + (l >> 2);
            const int i = ibase + nt * 8 + ((l & 3) << 1);
            float* p = dw + (size_t)o * N_IN + i;
            asm volatile("red.global.add.v2.f32 [%0], {%1,%2};"
                         :: "l"(p), "f"(acc[mt][nt][0]), "f"(acc[mt][nt][1]) : "memory");
            asm volatile("red.global.add.v2.f32 [%0], {%1,%2};"
                         :: "l"(p + 8 * N_IN), "f"(acc[mt][nt][2]), "f"(acc[mt][nt][3]) : "memory");
        }
    }
}

extern "C" void kernel_launch(void* const* d_in, const int* in_sizes, int n_in,
                              void* d_out, int out_size) {
    (void)in_sizes; (void)n_in;
    const float* gin  = (const float*)d_in[0];   // in_spikes  [T, B, N_IN]
    const float* gout = (const float*)d_in[1];   // out_spikes [T, B, N_OUT]
    float* dw = (float*)d_out;                   // [N_OUT, N_IN]

    cudaMemsetAsync(dw, 0, (size_t)out_size * sizeof(float), 0);

    dim3 grid(GT, NBS);
    stdp_main_kernel<<<grid, NTHR>>>(gin, gout, dw);

    dim3 cgrid((GT - 1) / CPC, NBS);             // 9 x 4 = 36 CTAs
    stdp_corr_kernel<<<cgrid, NTHR>>>(dw);
}